// round 2
// baseline (speedup 1.0000x reference)
#include <cuda_runtime.h>
#include <stdint.h>

#define NROW 4096
#define DIM  1024
#define NT   256

// Static device scratch (no runtime allocation allowed).
__device__ float g_X[(size_t)NROW * DIM];          // 16 MB normalized embeddings
__device__ float g_SIM[(size_t)NROW * NROW];       // 64 MB similarity matrix
__device__ unsigned char g_cls[NROW];
__device__ float g_rowloss[NROW];

// Monotone fp32 <-> uint32 key (ascending order preserved)
__device__ __forceinline__ unsigned int f2k(float f) {
    unsigned int u = __float_as_uint(f);
    return (u & 0x80000000u) ? ~u : (u | 0x80000000u);
}
__device__ __forceinline__ float k2f(unsigned int k) {
    unsigned int u = (k & 0x80000000u) ? (k & 0x7FFFFFFFu) : ~k;
    return __uint_as_float(u);
}

// ---------------------------------------------------------------------------
// Classes: the reference declares int64 targets, but JAX without x64 emits
// int32. Sniff the layout: view buffer as int32; if ALL odd words in the
// first 4096 words are zero, it is little-endian int64 (values < 256 so the
// high word is 0); otherwise it is int32. Only the first 16 KB are read
// during detection — safe under both layouts.
__global__ __launch_bounds__(1024) void cls_kernel(const int* __restrict__ tgt32) {
    __shared__ int s_any;
    const int t = threadIdx.x;
    if (t == 0) s_any = 0;
    __syncthreads();
    int any = 0;
    for (int j = t; j < NROW / 2; j += 1024)
        any |= (tgt32[2 * j + 1] != 0);
    if (any) atomicOr(&s_any, 1);
    __syncthreads();
    const bool is64 = (s_any == 0);
    for (int i = t; i < NROW; i += 1024)
        g_cls[i] = (unsigned char)(is64 ? tgt32[2 * i] : tgt32[i]);
}

// ---------------------------------------------------------------------------
__global__ __launch_bounds__(256) void normalize_kernel(const float* __restrict__ emb) {
    const int i = blockIdx.x;
    const int t = threadIdx.x;
    __shared__ float s[256];
    const float* e = emb + (size_t)i * DIM;
    float acc = 0.f;
    for (int k = t; k < DIM; k += 256) { float v = e[k]; acc += v * v; }
    s[t] = acc; __syncthreads();
    for (int o = 128; o > 0; o >>= 1) { if (t < o) s[t] += s[t + o]; __syncthreads(); }
    float norm = fmaxf(sqrtf(s[0]), 1e-12f);
    for (int k = t; k < DIM; k += 256) g_X[(size_t)i * DIM + k] = e[k] / norm;
}

// ---------------------------------------------------------------------------
// SIM = X * X^T, fp32 SIMT, 128x128 tile, 8x8 per thread, K-step 8.
__global__ __launch_bounds__(256, 2) void gemm_kernel() {
    __shared__ float As[8][128];
    __shared__ float Bs[8][128];
    const int bi = blockIdx.y * 128;
    const int bj = blockIdx.x * 128;
    const int t  = threadIdx.x;
    const int tx = t & 15;
    const int ty = t >> 4;
    const int lr = t >> 1;          // 0..127
    const int lc = (t & 1) * 4;     // 0 or 4

    float acc[8][8];
#pragma unroll
    for (int u = 0; u < 8; u++)
#pragma unroll
        for (int v = 0; v < 8; v++) acc[u][v] = 0.f;

    const float* Arow = g_X + (size_t)(bi + lr) * DIM + lc;
    const float* Brow = g_X + (size_t)(bj + lr) * DIM + lc;

    for (int k0 = 0; k0 < DIM; k0 += 8) {
        float4 a = *(const float4*)(Arow + k0);
        float4 b = *(const float4*)(Brow + k0);
        As[lc + 0][lr] = a.x; As[lc + 1][lr] = a.y; As[lc + 2][lr] = a.z; As[lc + 3][lr] = a.w;
        Bs[lc + 0][lr] = b.x; Bs[lc + 1][lr] = b.y; Bs[lc + 2][lr] = b.z; Bs[lc + 3][lr] = b.w;
        __syncthreads();
#pragma unroll
        for (int kk = 0; kk < 8; kk++) {
            float ar[8], bc[8];
#pragma unroll
            for (int u = 0; u < 8; u++) ar[u] = As[kk][ty * 8 + u];
#pragma unroll
            for (int v = 0; v < 8; v++) bc[v] = Bs[kk][tx * 8 + v];
#pragma unroll
            for (int u = 0; u < 8; u++)
#pragma unroll
                for (int v = 0; v < 8; v++) acc[u][v] = fmaf(ar[u], bc[v], acc[u][v]);
        }
        __syncthreads();
    }
#pragma unroll
    for (int u = 0; u < 8; u++) {
        float* dst = g_SIM + (size_t)(bi + ty * 8 + u) * NROW + bj + tx * 8;
        *(float4*)(dst + 0) = make_float4(acc[u][0], acc[u][1], acc[u][2], acc[u][3]);
        *(float4*)(dst + 4) = make_float4(acc[u][4], acc[u][5], acc[u][6], acc[u][7]);
    }
}

// ---------------------------------------------------------------------------
// Per-row: exact radix select of (drop+1)-th largest negative, then loss terms.
__global__ __launch_bounds__(NT) void row_loss_kernel() {
    __shared__ float s_v[NROW];            // 16 KB: sim row
    __shared__ unsigned char s_c[NROW];    // 4 KB : classes
    __shared__ unsigned int s_hist[256];
    __shared__ unsigned int s_scan[256];
    __shared__ float s_red[NT];
    __shared__ unsigned int sh_prefix, sh_r, sh_ceq;

    const int i = blockIdx.x;
    const int t = threadIdx.x;
    const unsigned char myc = g_cls[i];
    const float* row = g_SIM + (size_t)i * NROW;

    for (int j = t; j < NROW; j += NT) {
        s_v[j] = row[j];
        s_c[j] = g_cls[j];
    }
    __syncthreads();

    // ---- radix select: r-th LARGEST negative, r = drop+1 ----
    unsigned int prefix = 0;
    for (int round = 0; round < 4; round++) {
        const int shift = 24 - 8 * round;
        s_hist[t] = 0;
        __syncthreads();
        for (int j = t; j < NROW; j += NT) {
            if (s_c[j] != myc) {
                unsigned int k = f2k(s_v[j]);
                if (round == 0 || (k >> (shift + 8)) == prefix)
                    atomicAdd(&s_hist[(k >> shift) & 255u], 1u);
            }
        }
        __syncthreads();
        // parallel suffix sums: s_scan[b] = sum_{b'>=b} hist[b']
        s_scan[t] = s_hist[t];
        __syncthreads();
        for (int o = 1; o < 256; o <<= 1) {
            unsigned int w = (t + o < 256) ? s_scan[t + o] : 0u;
            __syncthreads();
            s_scan[t] += w;
            __syncthreads();
        }
        if (round == 0 && t == 0) {
            int K = (int)s_scan[0];  // number of negatives in this row
            int drop = max((int)floorf((float)K * 0.05f), 1);
            sh_r = (unsigned int)(drop + 1);
        }
        __syncthreads();
        unsigned int r   = sh_r;
        unsigned int ss  = s_scan[t];
        unsigned int ssn = (t < 255) ? s_scan[t + 1] : 0u;
        unsigned int h   = s_hist[t];
        __syncthreads();
        // unique bucket b: suffix(b) >= r and suffix(b+1) < r
        if (ss >= r && (t == 255 || ssn < r)) {
            sh_prefix = (prefix << 8) | (unsigned int)t;
            sh_r      = r - (ss - h);     // rank within this bucket (1-based)
            sh_ceq    = h;
        }
        __syncthreads();
        prefix = sh_prefix;
    }

    const float T = k2f(prefix);                    // == neg_thresh exactly
    const int   m = (int)sh_ceq + 1 - (int)sh_r;    // # kept negatives equal to T
    __syncthreads();

    // ---- pass 1: positives (pos_max, pos_loss, has_pos) ----
    const float thr = T + 0.1f;
    float pmax  = -1e30f;
    float ploss = 0.f;
    for (int j = t; j < NROW; j += NT) {
        if (s_c[j] == myc && j != i) {
            float v = s_v[j];
            pmax = fmaxf(pmax, v);
            if (v < thr) ploss += 1.0f - v;
        }
    }
    s_red[t] = pmax; __syncthreads();
    for (int o = NT / 2; o > 0; o >>= 1) { if (t < o) s_red[t] = fmaxf(s_red[t], s_red[t + o]); __syncthreads(); }
    pmax = s_red[0];
    __syncthreads();
    s_red[t] = ploss; __syncthreads();
    for (int o = NT / 2; o > 0; o >>= 1) { if (t < o) s_red[t] += s_red[t + o]; __syncthreads(); }
    ploss = s_red[0];
    __syncthreads();

    const float lower = fmaxf(0.6f, pmax) - 0.1f;

    // ---- pass 2: kept negatives strictly below T, above lower ----
    float ns = 0.f;
    for (int j = t; j < NROW; j += NT) {
        float v = s_v[j];
        if (s_c[j] != myc && v < T && v > lower) ns += v;
    }
    s_red[t] = ns; __syncthreads();
    for (int o = NT / 2; o > 0; o >>= 1) { if (t < o) s_red[t] += s_red[t + o]; __syncthreads(); }

    if (t == 0) {
        float loss = 0.f;
        if (pmax > -1e29f) {                       // has_pos
            loss = ploss + s_red[0];
            if (T > lower) loss += (float)m * T;   // ties at threshold (kept copies)
        }
        g_rowloss[i] = loss;
    }
}

// ---------------------------------------------------------------------------
__global__ void finalize_kernel(float* __restrict__ out) {
    __shared__ float s[1024];
    int t = threadIdx.x;
    float a = 0.f;
    for (int j = t; j < NROW; j += 1024) a += g_rowloss[j];
    s[t] = a; __syncthreads();
    for (int o = 512; o > 0; o >>= 1) { if (t < o) s[t] += s[t + o]; __syncthreads(); }
    if (t == 0) out[0] = s[0] / (float)NROW;
}

// ---------------------------------------------------------------------------
extern "C" void kernel_launch(void* const* d_in, const int* in_sizes, int n_in,
                              void* d_out, int out_size) {
    const float* emb   = (const float*)d_in[0];
    const int*   tgt32 = (const int*)d_in[1];
    float* out = (float*)d_out;

    cls_kernel<<<1, 1024>>>(tgt32);
    normalize_kernel<<<NROW, 256>>>(emb);
    gemm_kernel<<<dim3(32, 32), 256>>>();
    row_loss_kernel<<<NROW, NT>>>();
    finalize_kernel<<<1, 1024>>>(out);
}

// round 3
// speedup vs baseline: 4.3020x; 4.3020x over previous
#include <cuda_runtime.h>
#include <cuda_bf16.h>
#include <stdint.h>

#define NROW 4096
#define DIM  1024
#define NT   256
#define RS   40          // padded smem row stride (bf16 elems) for conflict-free ldmatrix

// Static device scratch (no runtime allocation allowed).
__device__ __nv_bfloat16 g_Xb[(size_t)NROW * DIM];   // 8 MB normalized embeddings (bf16)
__device__ float g_SIM[(size_t)NROW * NROW];         // 64 MB similarity matrix
__device__ unsigned char g_cls[NROW];
__device__ float g_rowloss[NROW];

// Monotone fp32 <-> uint32 key (ascending order preserved)
__device__ __forceinline__ unsigned int f2k(float f) {
    unsigned int u = __float_as_uint(f);
    return (u & 0x80000000u) ? ~u : (u | 0x80000000u);
}
__device__ __forceinline__ float k2f(unsigned int k) {
    unsigned int u = (k & 0x80000000u) ? (k & 0x7FFFFFFFu) : ~k;
    return __uint_as_float(u);
}

// ---------------------------------------------------------------------------
// Classes: reference declares int64 targets, but JAX without x64 emits int32.
// Sniff layout: if ALL odd int32 words are zero -> little-endian int64.
__global__ __launch_bounds__(1024) void cls_kernel(const int* __restrict__ tgt32) {
    __shared__ int s_any;
    const int t = threadIdx.x;
    if (t == 0) s_any = 0;
    __syncthreads();
    int any = 0;
    for (int j = t; j < NROW / 2; j += 1024)
        any |= (tgt32[2 * j + 1] != 0);
    if (any) atomicOr(&s_any, 1);
    __syncthreads();
    const bool is64 = (s_any == 0);
    for (int i = t; i < NROW; i += 1024)
        g_cls[i] = (unsigned char)(is64 ? tgt32[2 * i] : tgt32[i]);
}

// ---------------------------------------------------------------------------
__global__ __launch_bounds__(256) void normalize_kernel(const float* __restrict__ emb) {
    const int i = blockIdx.x;
    const int t = threadIdx.x;
    __shared__ float s[256];
    const float* e = emb + (size_t)i * DIM;
    float acc = 0.f;
    for (int k = t; k < DIM; k += 256) { float v = e[k]; acc += v * v; }
    s[t] = acc; __syncthreads();
    for (int o = 128; o > 0; o >>= 1) { if (t < o) s[t] += s[t + o]; __syncthreads(); }
    float norm = fmaxf(sqrtf(s[0]), 1e-12f);
    for (int k = t; k < DIM; k += 256)
        g_Xb[(size_t)i * DIM + k] = __float2bfloat16(e[k] / norm);
}

// ---------------------------------------------------------------------------
// SIM = X * X^T in bf16 tensor cores (mma.sync m16n8k16, fp32 accum).
// Block tile 128x128, K-stage 32, cp.async double buffering.
// 8 warps in 2(m) x 4(n); warp tile 64x32 = 4x4 fragments of m16n8.

__device__ __forceinline__ void cp16(unsigned int smem_dst, const void* gsrc) {
    asm volatile("cp.async.cg.shared.global [%0], [%1], 16;\n" :: "r"(smem_dst), "l"(gsrc));
}
__device__ __forceinline__ void cp_commit() { asm volatile("cp.async.commit_group;\n"); }
__device__ __forceinline__ void cp_wait0() { asm volatile("cp.async.wait_group 0;\n"); }

__global__ __launch_bounds__(256) void gemm_kernel() {
    __shared__ __nv_bfloat16 sA[2][128][RS];
    __shared__ __nv_bfloat16 sB[2][128][RS];

    const int t    = threadIdx.x;
    const int lane = t & 31;
    const int wid  = t >> 5;
    const int wm   = (wid >> 2) * 64;   // warp m offset (0 or 64)
    const int wn   = (wid & 3) * 32;    // warp n offset (0,32,64,96)
    const int bi   = blockIdx.y * 128;
    const int bj   = blockIdx.x * 128;

    float acc[4][4][4];
#pragma unroll
    for (int mt = 0; mt < 4; mt++)
#pragma unroll
        for (int nt = 0; nt < 4; nt++)
#pragma unroll
            for (int r = 0; r < 4; r++) acc[mt][nt][r] = 0.f;

    // stage loader: 512 16B chunks per tile (128 rows x 64B), 256 threads x 2
    auto load_stage = [&](int buf, int k0) {
#pragma unroll
        for (int c = t; c < 512; c += 256) {
            int row = c >> 2, off = (c & 3) * 8;
            cp16((unsigned int)__cvta_generic_to_shared(&sA[buf][row][off]),
                 g_Xb + (size_t)(bi + row) * DIM + k0 + off);
            cp16((unsigned int)__cvta_generic_to_shared(&sB[buf][row][off]),
                 g_Xb + (size_t)(bj + row) * DIM + k0 + off);
        }
    };

    load_stage(0, 0);
    cp_commit();
    cp_wait0();
    __syncthreads();

    for (int s = 0; s < DIM / 32; s++) {
        const int cbuf = s & 1;
        if (s + 1 < DIM / 32) {
            load_stage((s + 1) & 1, (s + 1) * 32);
            cp_commit();
        }
#pragma unroll
        for (int ks = 0; ks < 2; ks++) {
            unsigned int a[4][4], b[4][2];
#pragma unroll
            for (int mt = 0; mt < 4; mt++) {
                unsigned int addr = (unsigned int)__cvta_generic_to_shared(
                    &sA[cbuf][wm + mt * 16 + (lane & 15)][ks * 16 + (lane >> 4) * 8]);
                asm volatile("ldmatrix.sync.aligned.m8n8.x4.shared.b16 {%0,%1,%2,%3}, [%4];"
                             : "=r"(a[mt][0]), "=r"(a[mt][1]), "=r"(a[mt][2]), "=r"(a[mt][3])
                             : "r"(addr));
            }
#pragma unroll
            for (int nt = 0; nt < 4; nt++) {
                unsigned int addr = (unsigned int)__cvta_generic_to_shared(
                    &sB[cbuf][wn + nt * 8 + (lane & 7)][ks * 16 + ((lane >> 3) & 1) * 8]);
                asm volatile("ldmatrix.sync.aligned.m8n8.x2.shared.b16 {%0,%1}, [%2];"
                             : "=r"(b[nt][0]), "=r"(b[nt][1]) : "r"(addr));
            }
#pragma unroll
            for (int mt = 0; mt < 4; mt++)
#pragma unroll
                for (int nt = 0; nt < 4; nt++) {
                    asm volatile(
                        "mma.sync.aligned.m16n8k16.row.col.f32.bf16.bf16.f32 "
                        "{%0,%1,%2,%3},{%4,%5,%6,%7},{%8,%9},{%0,%1,%2,%3};"
                        : "+f"(acc[mt][nt][0]), "+f"(acc[mt][nt][1]),
                          "+f"(acc[mt][nt][2]), "+f"(acc[mt][nt][3])
                        : "r"(a[mt][0]), "r"(a[mt][1]), "r"(a[mt][2]), "r"(a[mt][3]),
                          "r"(b[nt][0]), "r"(b[nt][1]));
                }
        }
        if (s + 1 < DIM / 32) cp_wait0();
        __syncthreads();
    }

    // epilogue: c fragment m16n8 -> lane holds (row=l/4, col=2*(l%4)) and (row+8, ...)
#pragma unroll
    for (int mt = 0; mt < 4; mt++) {
#pragma unroll
        for (int nt = 0; nt < 4; nt++) {
            int r0 = bi + wm + mt * 16 + (lane >> 2);
            int c0 = bj + wn + nt * 8 + (lane & 3) * 2;
            *(float2*)(g_SIM + (size_t)r0 * NROW + c0) =
                make_float2(acc[mt][nt][0], acc[mt][nt][1]);
            *(float2*)(g_SIM + (size_t)(r0 + 8) * NROW + c0) =
                make_float2(acc[mt][nt][2], acc[mt][nt][3]);
        }
    }
}

// ---------------------------------------------------------------------------
// Per-row: exact radix select of (drop+1)-th largest negative, then loss terms.
__global__ __launch_bounds__(NT) void row_loss_kernel() {
    __shared__ float s_v[NROW];            // 16 KB: sim row
    __shared__ unsigned char s_c[NROW];    // 4 KB : classes
    __shared__ unsigned int s_hist[256];
    __shared__ unsigned int s_scan[256];
    __shared__ float s_red[NT];
    __shared__ unsigned int sh_prefix, sh_r, sh_ceq;

    const int i = blockIdx.x;
    const int t = threadIdx.x;
    const unsigned char myc = g_cls[i];
    const float* row = g_SIM + (size_t)i * NROW;

    for (int j = t; j < NROW; j += NT) {
        s_v[j] = row[j];
        s_c[j] = g_cls[j];
    }
    __syncthreads();

    // ---- radix select: r-th LARGEST negative, r = drop+1 ----
    unsigned int prefix = 0;
    for (int round = 0; round < 4; round++) {
        const int shift = 24 - 8 * round;
        s_hist[t] = 0;
        __syncthreads();
        for (int j = t; j < NROW; j += NT) {
            if (s_c[j] != myc) {
                unsigned int k = f2k(s_v[j]);
                if (round == 0 || (k >> (shift + 8)) == prefix)
                    atomicAdd(&s_hist[(k >> shift) & 255u], 1u);
            }
        }
        __syncthreads();
        s_scan[t] = s_hist[t];
        __syncthreads();
        for (int o = 1; o < 256; o <<= 1) {
            unsigned int w = (t + o < 256) ? s_scan[t + o] : 0u;
            __syncthreads();
            s_scan[t] += w;
            __syncthreads();
        }
        if (round == 0 && t == 0) {
            int K = (int)s_scan[0];
            int drop = max((int)floorf((float)K * 0.05f), 1);
            sh_r = (unsigned int)(drop + 1);
        }
        __syncthreads();
        unsigned int r   = sh_r;
        unsigned int ss  = s_scan[t];
        unsigned int ssn = (t < 255) ? s_scan[t + 1] : 0u;
        unsigned int h   = s_hist[t];
        __syncthreads();
        if (ss >= r && (t == 255 || ssn < r)) {
            sh_prefix = (prefix << 8) | (unsigned int)t;
            sh_r      = r - (ss - h);
            sh_ceq    = h;
        }
        __syncthreads();
        prefix = sh_prefix;
    }

    const float T = k2f(prefix);                    // == neg_thresh exactly
    const int   m = (int)sh_ceq + 1 - (int)sh_r;    // # kept negatives equal to T
    __syncthreads();

    // ---- pass 1: positives ----
    const float thr = T + 0.1f;
    float pmax  = -1e30f;
    float ploss = 0.f;
    for (int j = t; j < NROW; j += NT) {
        if (s_c[j] == myc && j != i) {
            float v = s_v[j];
            pmax = fmaxf(pmax, v);
            if (v < thr) ploss += 1.0f - v;
        }
    }
    s_red[t] = pmax; __syncthreads();
    for (int o = NT / 2; o > 0; o >>= 1) { if (t < o) s_red[t] = fmaxf(s_red[t], s_red[t + o]); __syncthreads(); }
    pmax = s_red[0];
    __syncthreads();
    s_red[t] = ploss; __syncthreads();
    for (int o = NT / 2; o > 0; o >>= 1) { if (t < o) s_red[t] += s_red[t + o]; __syncthreads(); }
    ploss = s_red[0];
    __syncthreads();

    const float lower = fmaxf(0.6f, pmax) - 0.1f;

    // ---- pass 2: kept negatives strictly below T, above lower ----
    float ns = 0.f;
    for (int j = t; j < NROW; j += NT) {
        float v = s_v[j];
        if (s_c[j] != myc && v < T && v > lower) ns += v;
    }
    s_red[t] = ns; __syncthreads();
    for (int o = NT / 2; o > 0; o >>= 1) { if (t < o) s_red[t] += s_red[t + o]; __syncthreads(); }

    if (t == 0) {
        float loss = 0.f;
        if (pmax > -1e29f) {                       // has_pos
            loss = ploss + s_red[0];
            if (T > lower) loss += (float)m * T;   // ties at threshold (kept copies)
        }
        g_rowloss[i] = loss;
    }
}

// ---------------------------------------------------------------------------
__global__ void finalize_kernel(float* __restrict__ out) {
    __shared__ float s[1024];
    int t = threadIdx.x;
    float a = 0.f;
    for (int j = t; j < NROW; j += 1024) a += g_rowloss[j];
    s[t] = a; __syncthreads();
    for (int o = 512; o > 0; o >>= 1) { if (t < o) s[t] += s[t + o]; __syncthreads(); }
    if (t == 0) out[0] = s[0] / (float)NROW;
}

// ---------------------------------------------------------------------------
extern "C" void kernel_launch(void* const* d_in, const int* in_sizes, int n_in,
                              void* d_out, int out_size) {
    const float* emb   = (const float*)d_in[0];
    const int*   tgt32 = (const int*)d_in[1];
    float* out = (float*)d_out;

    cls_kernel<<<1, 1024>>>(tgt32);
    normalize_kernel<<<NROW, 256>>>(emb);
    gemm_kernel<<<dim3(32, 32), 256>>>();
    row_loss_kernel<<<NROW, NT>>>();
    finalize_kernel<<<1, 1024>>>(out);
}